// round 10
// baseline (speedup 1.0000x reference)
#include <cuda_runtime.h>
#include <math.h>

// ---------------------------------------------------------------------------
// AdaptivePatchEmbedding — B=128,C=32,S=336 -> N=4096, R=7, TARGET=6, D=512
// Straight-through gumbel == one-hot: compute only selected expert per region.
// Unique patch rows per region: P=8 ->6, P=16/24 ->2, P=48 ->1.
// TWO launches: router (pe table + expert compaction) -> persistent fused
// embed, warp-autonomous chunks of 6 unique rows x 64 cols, 12 acc regs per
// thread -> 5 blocks/SM (62.5% occ). W staged in smem (20 rows), static
// strided chunk assignment, no atomics / barriers in the hot path.
// ---------------------------------------------------------------------------

#define NREG 28672            // 4096 * 7
#define XP_ELEMS 88080384LL   // 4096 * 42 * 512

__device__ int   g_counts[4];   // zero at module load; embed resets at end
__device__ int   g_done;
__device__ int   g_lists[4 * NREG];
__device__ float g_pe[42 * 512];

// --------------------------- stage 1: router + pe table ---------------------
__global__ void __launch_bounds__(64) router_kernel(
    const float* __restrict__ x,  const float* __restrict__ un,
    const float* __restrict__ W1, const float* __restrict__ b1,
    const float* __restrict__ W2, const float* __restrict__ b2,
    float* __restrict__ out, int write_mode)
{
    __shared__ float W1s[48 * 64];
    __shared__ float W2s[256];
    __shared__ float b1s[64];
    int tid = threadIdx.x;
    int region = blockIdx.x * 64 + tid;      // grid = 448 -> exactly 28672

    // pe table: one dim-pair per thread, first 10752 threads; fp64 exp
    // latency hides under the MLP below.
    if (region < 10752) {
        int pos = region >> 8;               // [0,42)
        int tp  = region & 255;              // dim pair [0,256)
        double dv = exp((double)(2 * tp) * -(log(10000.0) / 512.0));
        float ang = (float)((double)pos * dv);
        float2 sc = make_float2(sinf(ang), cosf(ang));
        *(float2*)&g_pe[pos * 512 + 2 * tp] = sc;
    }

    for (int i = tid; i < 768; i += 64) ((float4*)W1s)[i] = ((const float4*)W1)[i];
    ((float4*)W2s)[tid] = ((const float4*)W2)[tid];
    b1s[tid] = b1[tid];
    __syncthreads();

    int n = region / 7, r = region - n * 7;

    float xr[48];
    const float4* xp = (const float4*)x + n * 84 + r * 12;
#pragma unroll
    for (int v = 0; v < 12; v++) {
        float4 t4 = xp[v];
        xr[4*v+0] = t4.x; xr[4*v+1] = t4.y; xr[4*v+2] = t4.z; xr[4*v+3] = t4.w;
    }

    float lg0 = b2[0], lg1 = b2[1], lg2 = b2[2], lg3 = b2[3];
#pragma unroll 2
    for (int k = 0; k < 64; k++) {
        float s = b1s[k];
#pragma unroll
        for (int j = 0; j < 48; j++) s = fmaf(xr[j], W1s[j * 64 + k], s);
        s = fmaxf(s, 0.0f);
        lg0 = fmaf(s, W2s[k*4+0], lg0);
        lg1 = fmaf(s, W2s[k*4+1], lg1);
        lg2 = fmaf(s, W2s[k*4+2], lg2);
        lg3 = fmaf(s, W2s[k*4+3], lg3);
    }

    const float* up = un + (long long)region * 4;
    float z0 = lg0 - logf(-logf(up[0] + 1e-10f) + 1e-10f);
    float z1 = lg1 - logf(-logf(up[1] + 1e-10f) + 1e-10f);
    float z2 = lg2 - logf(-logf(up[2] + 1e-10f) + 1e-10f);
    float z3 = lg3 - logf(-logf(up[3] + 1e-10f) + 1e-10f);

    int e = 0; float best = z0;              // first-max semantics like jnp.argmax
    if (z1 > best) { best = z1; e = 1; }
    if (z2 > best) { best = z2; e = 2; }
    if (z3 > best) { best = z3; e = 3; }

    int slot = atomicAdd(&g_counts[e], 1);
    g_lists[e * NREG + slot] = region;

    if (write_mode >= 2) out[XP_ELEMS + 1 + (long long)r * 4096 + n] = (float)e;
    if (write_mode >= 1 && region == 0) out[XP_ELEMS] = 32.0f;
}

// --------------------------- stage 2: warp-autonomous fused embed -----------
// Chunk = 6 unique rows x 64 cols (one warp; lane owns 1 float2 of cols).
// K = 7-48/P repeats, U = ceil(6/K) unique rows/region, RPC = 6/U regions.
// Chunk id: low 3 bits = col slice (8 x 64), high bits = region group.
// Warp gw takes chunks gw, gw+NW, ...  acc = 12 regs/thread.
template<int P, int SR>
__device__ __forceinline__ void embed_expert(
    const float* __restrict__ x, const float2* __restrict__ Wf2,
    float2* __restrict__ out2, const float2* Wsm2, int gw, int NW)
{
    constexpr int E   = (P == 8) ? 0 : (P == 16) ? 1 : (P == 24) ? 2 : 3;
    constexpr int K   = 7 - 48 / P;
    constexpr int U   = (6 + K - 1) / K;
    constexpr int RPC = 6 / U;

    const int cnt  = g_counts[E];
    const int nch  = ((cnt + RPC - 1) / RPC) << 3;
    const int lane = threadIdx.x & 31;
    const int* lst0 = g_lists + E * NREG;
    const float4* x4 = (const float4*)x;

    for (int c = gw; c < nch; c += NW) {
        const int colf2 = ((c & 7) << 5) + lane;     // float2 col index [0,256)
        const int base  = (c >> 3) * RPC;
        const int nval  = min(RPC, cnt - base);

        // per-unique-row float4 offsets into x (clamped for tail chunks)
        int aoff[6];
#pragma unroll
        for (int rr = 0; rr < 6; rr++) {
            int reg  = rr / U;
            int ridx = reg < nval ? reg : nval - 1;
            int rid  = __ldg(&lst0[base + ridx]);
            int n = rid / 7, r = rid - n * 7;
            aoff[rr] = n * 84 + r * 12 + (rr % U) * (P / 4);
        }

        float2 acc[6];
#pragma unroll
        for (int i = 0; i < 6; i++) acc[i] = make_float2(0.f, 0.f);

#pragma unroll
        for (int k4 = 0; k4 < P / 4; k4++) {
            const int k = k4 * 4;
            float2 b0 = (k + 0 < SR) ? Wsm2[(k + 0) * 256 + colf2]
                                     : __ldg(&Wf2[(k + 0) * 256 + colf2]);
            float2 b1 = (k + 1 < SR) ? Wsm2[(k + 1) * 256 + colf2]
                                     : __ldg(&Wf2[(k + 1) * 256 + colf2]);
            float2 b2 = (k + 2 < SR) ? Wsm2[(k + 2) * 256 + colf2]
                                     : __ldg(&Wf2[(k + 2) * 256 + colf2]);
            float2 b3 = (k + 3 < SR) ? Wsm2[(k + 3) * 256 + colf2]
                                     : __ldg(&Wf2[(k + 3) * 256 + colf2]);
#pragma unroll
            for (int rr = 0; rr < 6; rr++) {
                float4 a = __ldg(&x4[aoff[rr] + k4]);    // warp-uniform
                acc[rr].x = fmaf(a.x, b0.x, acc[rr].x);
                acc[rr].y = fmaf(a.x, b0.y, acc[rr].y);
                acc[rr].x = fmaf(a.y, b1.x, acc[rr].x);
                acc[rr].y = fmaf(a.y, b1.y, acc[rr].y);
                acc[rr].x = fmaf(a.z, b2.x, acc[rr].x);
                acc[rr].y = fmaf(a.z, b2.y, acc[rr].y);
                acc[rr].x = fmaf(a.w, b3.x, acc[rr].x);
                acc[rr].y = fmaf(a.w, b3.y, acc[rr].y);
            }
        }

        const float2* pe2 = (const float2*)g_pe;
#pragma unroll
        for (int rr = 0; rr < 6; rr++) {
            int reg = rr / U;
            int q   = rr % U;
            if (reg >= nval) continue;
            int rid = __ldg(&lst0[base + reg]);
            int n = rid / 7, r = rid - n * 7;
#pragma unroll
            for (int t = q * K; t < ((q + 1) * K < 6 ? (q + 1) * K : 6); t++) {
                int pos = r * 6 + t;
                float2 p = __ldg(&pe2[pos * 256 + colf2]);
                float2 v = make_float2(acc[rr].x + p.x, acc[rr].y + p.y);
                __stcs(&out2[(long long)n * 10752 + pos * 256 + colf2], v);
            }
        }
    }
}

template<int SR>
__device__ __forceinline__ void stage_w(const float4* __restrict__ W4,
                                        float4* Wsm4) {
    for (int i = threadIdx.x; i < SR * 128; i += 256) Wsm4[i] = W4[i];
}

__global__ void __launch_bounds__(256, 5) embed_fused_kernel(
    const float* __restrict__ x,
    const float4* __restrict__ We0, const float4* __restrict__ We1,
    const float4* __restrict__ We2, const float4* __restrict__ We3,
    float2* __restrict__ out2)
{
    extern __shared__ float sm[];
    float4* Wsm4 = (float4*)sm;            // 20 rows * 128 float4 = 40 KB
    const float2* Wsm2 = (const float2*)sm;

    const int gw = blockIdx.x * 8 + (threadIdx.x >> 5);
    const int NW = gridDim.x * 8;

    stage_w<20>(We3, Wsm4);
    __syncthreads();
    embed_expert<48, 20>(x, (const float2*)We3, out2, Wsm2, gw, NW);
    __syncthreads();

    stage_w<20>(We2, Wsm4);
    __syncthreads();
    embed_expert<24, 20>(x, (const float2*)We2, out2, Wsm2, gw, NW);
    __syncthreads();

    stage_w<16>(We1, Wsm4);
    __syncthreads();
    embed_expert<16, 16>(x, (const float2*)We1, out2, Wsm2, gw, NW);
    __syncthreads();

    stage_w<8>(We0, Wsm4);
    __syncthreads();
    embed_expert< 8,  8>(x, (const float2*)We0, out2, Wsm2, gw, NW);

    // last block out resets routing state for the next graph replay
    if (threadIdx.x == 0) {
        int d = atomicAdd(&g_done, 1);
        if (d == (int)gridDim.x - 1) {
            g_counts[0] = 0; g_counts[1] = 0; g_counts[2] = 0; g_counts[3] = 0;
            g_done = 0;
        }
    }
}

// --------------------------- launch ------------------------------------------
extern "C" void kernel_launch(void* const* d_in, const int* in_sizes, int n_in,
                              void* d_out, int out_size) {
    const float* x  = (const float*)d_in[0];
    const float* un = (const float*)d_in[1];
    const float* W1 = (const float*)d_in[2];
    const float* b1 = (const float*)d_in[3];
    const float* W2 = (const float*)d_in[4];
    const float* b2 = (const float*)d_in[5];
    const float4* We0 = (const float4*)d_in[6];
    const float4* We1 = (const float4*)d_in[7];
    const float4* We2 = (const float4*)d_in[8];
    const float4* We3 = (const float4*)d_in[9];
    float*  out  = (float*)d_out;
    float2* out2 = (float2*)d_out;

    int write_mode = 0;
    if ((long long)out_size >= XP_ELEMS + 1 + 28672) write_mode = 2;
    else if ((long long)out_size >= XP_ELEMS + 1)    write_mode = 1;

    const int SMEM = 20 * 512 * 4;   // 40960 bytes -> 5 blocks/SM
    cudaFuncSetAttribute(embed_fused_kernel,
                         cudaFuncAttributeMaxDynamicSharedMemorySize, SMEM);

    router_kernel<<<448, 64>>>(x, un, W1, b1, W2, b2, out, write_mode);
    embed_fused_kernel<<<740, 256, SMEM>>>(x, We0, We1, We2, We3, out2);
    (void)in_sizes; (void)n_in;
}

// round 11
// speedup vs baseline: 1.2475x; 1.2475x over previous
#include <cuda_runtime.h>
#include <math.h>

// ---------------------------------------------------------------------------
// AdaptivePatchEmbedding — B=128,C=32,S=336 -> N=4096, R=7, TARGET=6, D=512
// Straight-through gumbel == one-hot: compute only selected expert per region.
// Unique patch rows per region: P=8 ->6, P=16/24 ->2, P=48 ->1.
// TWO launches: router (pe table + expert compaction) -> persistent fused
// embed, fully WARP-AUTONOMOUS and BARRIER-FREE: per-expert strided loops run
// back-to-back per warp (no block sync anywhere), all operands through L1
// (per-expert phases keep one ~<=49KB W table + 86KB pe hot; fits 228KB L1).
// ---------------------------------------------------------------------------

#define NREG 28672            // 4096 * 7
#define XP_ELEMS 88080384LL   // 4096 * 42 * 512

__device__ int   g_counts[4];   // zero at module load; embed resets at end
__device__ int   g_done;
__device__ int   g_lists[4 * NREG];
__device__ float g_pe[42 * 512];

// --------------------------- stage 1: router + pe table ---------------------
__global__ void __launch_bounds__(64) router_kernel(
    const float* __restrict__ x,  const float* __restrict__ un,
    const float* __restrict__ W1, const float* __restrict__ b1,
    const float* __restrict__ W2, const float* __restrict__ b2,
    float* __restrict__ out, int write_mode)
{
    __shared__ float W1s[48 * 64];
    __shared__ float W2s[256];
    __shared__ float b1s[64];
    int tid = threadIdx.x;
    int region = blockIdx.x * 64 + tid;      // grid = 448 -> exactly 28672

    // pe table: one dim-pair per thread, first 10752 threads; fp64 exp
    // latency hides under the MLP below.
    if (region < 10752) {
        int pos = region >> 8;               // [0,42)
        int tp  = region & 255;              // dim pair [0,256)
        double dv = exp((double)(2 * tp) * -(log(10000.0) / 512.0));
        float ang = (float)((double)pos * dv);
        float2 sc = make_float2(sinf(ang), cosf(ang));
        *(float2*)&g_pe[pos * 512 + 2 * tp] = sc;
    }

    for (int i = tid; i < 768; i += 64) ((float4*)W1s)[i] = ((const float4*)W1)[i];
    ((float4*)W2s)[tid] = ((const float4*)W2)[tid];
    b1s[tid] = b1[tid];
    __syncthreads();

    int n = region / 7, r = region - n * 7;

    float xr[48];
    const float4* xp = (const float4*)x + n * 84 + r * 12;
#pragma unroll
    for (int v = 0; v < 12; v++) {
        float4 t4 = xp[v];
        xr[4*v+0] = t4.x; xr[4*v+1] = t4.y; xr[4*v+2] = t4.z; xr[4*v+3] = t4.w;
    }

    float lg0 = b2[0], lg1 = b2[1], lg2 = b2[2], lg3 = b2[3];
#pragma unroll 2
    for (int k = 0; k < 64; k++) {
        float s = b1s[k];
#pragma unroll
        for (int j = 0; j < 48; j++) s = fmaf(xr[j], W1s[j * 64 + k], s);
        s = fmaxf(s, 0.0f);
        lg0 = fmaf(s, W2s[k*4+0], lg0);
        lg1 = fmaf(s, W2s[k*4+1], lg1);
        lg2 = fmaf(s, W2s[k*4+2], lg2);
        lg3 = fmaf(s, W2s[k*4+3], lg3);
    }

    const float* up = un + (long long)region * 4;
    float z0 = lg0 - logf(-logf(up[0] + 1e-10f) + 1e-10f);
    float z1 = lg1 - logf(-logf(up[1] + 1e-10f) + 1e-10f);
    float z2 = lg2 - logf(-logf(up[2] + 1e-10f) + 1e-10f);
    float z3 = lg3 - logf(-logf(up[3] + 1e-10f) + 1e-10f);

    int e = 0; float best = z0;              // first-max semantics like jnp.argmax
    if (z1 > best) { best = z1; e = 1; }
    if (z2 > best) { best = z2; e = 2; }
    if (z3 > best) { best = z3; e = 3; }

    int slot = atomicAdd(&g_counts[e], 1);
    g_lists[e * NREG + slot] = region;

    if (write_mode >= 2) out[XP_ELEMS + 1 + (long long)r * 4096 + n] = (float)e;
    if (write_mode >= 1 && region == 0) out[XP_ELEMS] = 32.0f;
}

// --------------------------- stage 2: warp-autonomous fused embed -----------
// Per expert P: K = 7-48/P repeats, U = ceil(6/K) unique rows/region,
// RPC = 6/U regions per warp-chunk (6 unique rows x 128 float4 cols; lane
// owns 1 float4, chunk low 2 bits select the col quarter). Warp gw takes
// chunks gw, gw+NW, ... All operands via __ldg (L1). No atomics, no barriers.
template<int P>
__device__ __forceinline__ void embed_expert(
    const float* __restrict__ x, const float4* __restrict__ W4,
    float4* __restrict__ out4, int gw, int NW)
{
    constexpr int E   = (P == 8) ? 0 : (P == 16) ? 1 : (P == 24) ? 2 : 3;
    constexpr int K   = 7 - 48 / P;
    constexpr int U   = (6 + K - 1) / K;
    constexpr int RPC = 6 / U;

    const int cnt = g_counts[E];
    const int nch = ((cnt + RPC - 1) / RPC) << 2;
    const int lane = threadIdx.x & 31;
    const int* lst0 = g_lists + E * NREG;
    const float2* x2 = (const float2*)x;

    for (int c = gw; c < nch; c += NW) {
        const int quarter = c & 3;
        const int base    = (c >> 2) * RPC;
        const int nval    = min(RPC, cnt - base);
        const int txq     = quarter * 32 + lane;        // float4 col index

        // per-unique-row float2 offsets into x (clamped for tail chunks)
        int aoff[6];
#pragma unroll
        for (int rr = 0; rr < 6; rr++) {
            int reg  = rr / U;
            int ridx = reg < nval ? reg : nval - 1;
            int rid  = __ldg(&lst0[base + ridx]);
            int n = rid / 7, r = rid - n * 7;
            aoff[rr] = n * 168 + r * 24 + (rr % U) * (P / 2);
        }

        float4 acc[6];
#pragma unroll
        for (int i = 0; i < 6; i++) acc[i] = make_float4(0.f, 0.f, 0.f, 0.f);

#pragma unroll
        for (int k = 0; k < P; k += 2) {
            float4 b0 = __ldg(&W4[k * 128 + txq]);
            float4 b1 = __ldg(&W4[(k + 1) * 128 + txq]);
#pragma unroll
            for (int rr = 0; rr < 6; rr++) {
                float2 a = __ldg(&x2[aoff[rr] + (k >> 1)]);   // warp-uniform
                acc[rr].x = fmaf(a.x, b0.x, acc[rr].x);
                acc[rr].y = fmaf(a.x, b0.y, acc[rr].y);
                acc[rr].z = fmaf(a.x, b0.z, acc[rr].z);
                acc[rr].w = fmaf(a.x, b0.w, acc[rr].w);
                acc[rr].x = fmaf(a.y, b1.x, acc[rr].x);
                acc[rr].y = fmaf(a.y, b1.y, acc[rr].y);
                acc[rr].z = fmaf(a.y, b1.z, acc[rr].z);
                acc[rr].w = fmaf(a.y, b1.w, acc[rr].w);
            }
        }

        const float4* pe4 = (const float4*)g_pe;
#pragma unroll
        for (int rr = 0; rr < 6; rr++) {
            int reg = rr / U;
            int q   = rr % U;
            if (reg >= nval) continue;
            int rid = __ldg(&lst0[base + reg]);
            int n = rid / 7, r = rid - n * 7;
#pragma unroll
            for (int t = q * K; t < ((q + 1) * K < 6 ? (q + 1) * K : 6); t++) {
                int pos = r * 6 + t;
                float4 p = __ldg(&pe4[pos * 128 + txq]);
                float4 v = make_float4(acc[rr].x + p.x, acc[rr].y + p.y,
                                       acc[rr].z + p.z, acc[rr].w + p.w);
                __stcs(&out4[(long long)n * 5376 + pos * 128 + txq], v);
            }
        }
    }
}

__global__ void __launch_bounds__(256, 4) embed_fused_kernel(
    const float* __restrict__ x,
    const float4* __restrict__ We0, const float4* __restrict__ We1,
    const float4* __restrict__ We2, const float4* __restrict__ We3,
    float4* __restrict__ out4)
{
    const int gw = blockIdx.x * 8 + (threadIdx.x >> 5);
    const int NW = gridDim.x * 8;

    // back-to-back per-expert phases, NO barriers: warps drift independently;
    // at any instant ~one W table (+pe) is hot in L1.
    embed_expert<48>(x, We3, out4, gw, NW);
    embed_expert<24>(x, We2, out4, gw, NW);
    embed_expert<16>(x, We1, out4, gw, NW);
    embed_expert< 8>(x, We0, out4, gw, NW);

    // last block out resets routing state for the next graph replay
    __syncthreads();
    if (threadIdx.x == 0) {
        int d = atomicAdd(&g_done, 1);
        if (d == (int)gridDim.x - 1) {
            g_counts[0] = 0; g_counts[1] = 0; g_counts[2] = 0; g_counts[3] = 0;
            g_done = 0;
        }
    }
}

// --------------------------- launch ------------------------------------------
extern "C" void kernel_launch(void* const* d_in, const int* in_sizes, int n_in,
                              void* d_out, int out_size) {
    const float* x  = (const float*)d_in[0];
    const float* un = (const float*)d_in[1];
    const float* W1 = (const float*)d_in[2];
    const float* b1 = (const float*)d_in[3];
    const float* W2 = (const float*)d_in[4];
    const float* b2 = (const float*)d_in[5];
    const float4* We0 = (const float4*)d_in[6];
    const float4* We1 = (const float4*)d_in[7];
    const float4* We2 = (const float4*)d_in[8];
    const float4* We3 = (const float4*)d_in[9];
    float*  out  = (float*)d_out;
    float4* out4 = (float4*)d_out;

    int write_mode = 0;
    if ((long long)out_size >= XP_ELEMS + 1 + 28672) write_mode = 2;
    else if ((long long)out_size >= XP_ELEMS + 1)    write_mode = 1;

    router_kernel<<<448, 64>>>(x, un, W1, b1, W2, b2, out, write_mode);
    embed_fused_kernel<<<592, 256>>>(x, We0, We1, We2, We3, out4);
    (void)in_sizes; (void)n_in;
}

// round 12
// speedup vs baseline: 1.8133x; 1.4536x over previous
#include <cuda_runtime.h>
#include <math.h>

// ---------------------------------------------------------------------------
// AdaptivePatchEmbedding — B=128,C=32,S=336 -> N=4096, R=7, TARGET=6, D=512
// Straight-through gumbel == one-hot: compute only selected expert per region.
// Unique patch rows per region: P=8 ->6, P=16/24 ->2, P=48 ->1.
// TWO launches: router (pe table + expert compaction) -> persistent fused
// embed (R5-proven block-synchronous per-expert phases, smem-staged W,
// per-expert atomic cursors) with float4 a-loads (k+=4) in the inner loop.
// ---------------------------------------------------------------------------

#define NREG 28672            // 4096 * 7
#define XP_ELEMS 88080384LL   // 4096 * 42 * 512

__device__ int   g_counts[4];   // zero at module load; embed resets at end
__device__ int   g_cursor[4];
__device__ int   g_done;
__device__ int   g_lists[4 * NREG];
__device__ float g_pe[42 * 512];

// --------------------------- stage 1: router + pe table ---------------------
__global__ void __launch_bounds__(64) router_kernel(
    const float* __restrict__ x,  const float* __restrict__ un,
    const float* __restrict__ W1, const float* __restrict__ b1,
    const float* __restrict__ W2, const float* __restrict__ b2,
    float* __restrict__ out, int write_mode)
{
    __shared__ float W1s[48 * 64];
    __shared__ float W2s[256];
    __shared__ float b1s[64];
    int tid = threadIdx.x;
    int region = blockIdx.x * 64 + tid;      // grid = 448 -> exactly 28672

    // pe table: one dim-pair per thread, first 10752 threads; fp64 exp
    // latency hides under the MLP below.
    if (region < 10752) {
        int pos = region >> 8;               // [0,42)
        int tp  = region & 255;              // dim pair [0,256)
        double dv = exp((double)(2 * tp) * -(log(10000.0) / 512.0));
        float ang = (float)((double)pos * dv);
        float2 sc = make_float2(sinf(ang), cosf(ang));
        *(float2*)&g_pe[pos * 512 + 2 * tp] = sc;
    }

    for (int i = tid; i < 768; i += 64) ((float4*)W1s)[i] = ((const float4*)W1)[i];
    ((float4*)W2s)[tid] = ((const float4*)W2)[tid];
    b1s[tid] = b1[tid];
    __syncthreads();

    int n = region / 7, r = region - n * 7;

    float xr[48];
    const float4* xp = (const float4*)x + n * 84 + r * 12;
#pragma unroll
    for (int v = 0; v < 12; v++) {
        float4 t4 = xp[v];
        xr[4*v+0] = t4.x; xr[4*v+1] = t4.y; xr[4*v+2] = t4.z; xr[4*v+3] = t4.w;
    }

    float lg0 = b2[0], lg1 = b2[1], lg2 = b2[2], lg3 = b2[3];
#pragma unroll 2
    for (int k = 0; k < 64; k++) {
        float s = b1s[k];
#pragma unroll
        for (int j = 0; j < 48; j++) s = fmaf(xr[j], W1s[j * 64 + k], s);
        s = fmaxf(s, 0.0f);
        lg0 = fmaf(s, W2s[k*4+0], lg0);
        lg1 = fmaf(s, W2s[k*4+1], lg1);
        lg2 = fmaf(s, W2s[k*4+2], lg2);
        lg3 = fmaf(s, W2s[k*4+3], lg3);
    }

    const float* up = un + (long long)region * 4;
    float z0 = lg0 - logf(-logf(up[0] + 1e-10f) + 1e-10f);
    float z1 = lg1 - logf(-logf(up[1] + 1e-10f) + 1e-10f);
    float z2 = lg2 - logf(-logf(up[2] + 1e-10f) + 1e-10f);
    float z3 = lg3 - logf(-logf(up[3] + 1e-10f) + 1e-10f);

    int e = 0; float best = z0;              // first-max semantics like jnp.argmax
    if (z1 > best) { best = z1; e = 1; }
    if (z2 > best) { best = z2; e = 2; }
    if (z3 > best) { best = z3; e = 3; }

    int slot = atomicAdd(&g_counts[e], 1);
    g_lists[e * NREG + slot] = region;

    if (write_mode >= 2) out[XP_ELEMS + 1 + (long long)r * 4096 + n] = (float)e;
    if (write_mode >= 1 && region == 0) out[XP_ELEMS] = 32.0f;
}

// --------------------------- stage 2: persistent fused embed ----------------
// 12 unique rows per chunk; thread (tx in [0,128), ty in {0,1}) owns 6 rows x 4
// cols. For P: K = 7-48/P repeats per unique row, U = ceil(6/K) unique
// rows/region, RPB = 12/U regions per chunk. Per-expert atomic cursors.
template<int P, bool WSM>
__device__ __forceinline__ void embed_expert(
    const float4* __restrict__ x4, const float4* __restrict__ W4,
    float4* __restrict__ out4, float* Wsm, float* xrs, int* ibuf)
{
    constexpr int E   = (P == 8) ? 0 : (P == 16) ? 1 : (P == 24) ? 2 : 3;
    constexpr int K   = 7 - 48 / P;
    constexpr int U   = (6 + K - 1) / K;
    constexpr int RPB = 12 / U;

    const int tid = threadIdx.x;
    const int cnt = g_counts[E];

    if (WSM) {
        for (int i = tid; i < P * 128; i += 256)
            ((float4*)Wsm)[i] = W4[i];
    }
    const int tx = tid & 127, ty = tid >> 7;

    int aoff[6];
#pragma unroll
    for (int rr = 0; rr < 6; rr++) {
        int row = ty * 6 + rr;
        aoff[rr] = (row / U) * 48 + (row % U) * P;   // multiple of 4 floats
    }

    for (;;) {
        if (tid == 0) ibuf[15] = atomicAdd(&g_cursor[E], 1);
        __syncthreads();
        int base = ibuf[15] * RPB;
        if (base >= cnt) break;
        int nval = min(RPB, cnt - base);
        if (tid < nval) ibuf[tid] = g_lists[E * NREG + base + tid];
        __syncthreads();

        for (int i = tid; i < nval * 12; i += 256) {
            int reg = i / 12, v = i - reg * 12;
            int rid = ibuf[reg];
            int n = rid / 7, r = rid - n * 7;
            ((float4*)xrs)[reg * 12 + v] = __ldg(&x4[n * 84 + r * 12 + v]);
        }
        __syncthreads();

        float4 acc[6];
#pragma unroll
        for (int i = 0; i < 6; i++) acc[i] = make_float4(0.f, 0.f, 0.f, 0.f);

#pragma unroll
        for (int k = 0; k < P; k += 4) {
            float4 b0 = WSM ? ((const float4*)Wsm)[(k + 0) * 128 + tx]
                            : __ldg(&W4[(k + 0) * 128 + tx]);
            float4 b1 = WSM ? ((const float4*)Wsm)[(k + 1) * 128 + tx]
                            : __ldg(&W4[(k + 1) * 128 + tx]);
            float4 b2 = WSM ? ((const float4*)Wsm)[(k + 2) * 128 + tx]
                            : __ldg(&W4[(k + 2) * 128 + tx]);
            float4 b3 = WSM ? ((const float4*)Wsm)[(k + 3) * 128 + tx]
                            : __ldg(&W4[(k + 3) * 128 + tx]);
#pragma unroll
            for (int rr = 0; rr < 6; rr++) {
                float4 a = *(const float4*)&xrs[aoff[rr] + k];   // 1 LDS.128
                acc[rr].x = fmaf(a.x, b0.x, acc[rr].x);
                acc[rr].y = fmaf(a.x, b0.y, acc[rr].y);
                acc[rr].z = fmaf(a.x, b0.z, acc[rr].z);
                acc[rr].w = fmaf(a.x, b0.w, acc[rr].w);
                acc[rr].x = fmaf(a.y, b1.x, acc[rr].x);
                acc[rr].y = fmaf(a.y, b1.y, acc[rr].y);
                acc[rr].z = fmaf(a.y, b1.z, acc[rr].z);
                acc[rr].w = fmaf(a.y, b1.w, acc[rr].w);
                acc[rr].x = fmaf(a.z, b2.x, acc[rr].x);
                acc[rr].y = fmaf(a.z, b2.y, acc[rr].y);
                acc[rr].z = fmaf(a.z, b2.z, acc[rr].z);
                acc[rr].w = fmaf(a.z, b2.w, acc[rr].w);
                acc[rr].x = fmaf(a.w, b3.x, acc[rr].x);
                acc[rr].y = fmaf(a.w, b3.y, acc[rr].y);
                acc[rr].z = fmaf(a.w, b3.z, acc[rr].z);
                acc[rr].w = fmaf(a.w, b3.w, acc[rr].w);
            }
        }

        const float4* pe4 = (const float4*)g_pe;
#pragma unroll
        for (int rr = 0; rr < 6; rr++) {
            int row = ty * 6 + rr;
            int reg = row / U;
            int q   = row % U;
            if (reg >= nval) continue;
            int rid = ibuf[reg];
            int n = rid / 7, r = rid - n * 7;
#pragma unroll
            for (int t = q * K; t < ((q + 1) * K < 6 ? (q + 1) * K : 6); t++) {
                int pos = r * 6 + t;
                float4 p = __ldg(&pe4[pos * 128 + tx]);
                float4 v = make_float4(acc[rr].x + p.x, acc[rr].y + p.y,
                                       acc[rr].z + p.z, acc[rr].w + p.w);
                __stcs(&out4[(long long)n * 5376 + pos * 128 + tx], v);
            }
        }
        __syncthreads();
    }
    __syncthreads();   // all threads done with ibuf before next expert reuses it
}

__global__ void __launch_bounds__(256, 4) embed_fused_kernel(
    const float4* __restrict__ x4,
    const float4* __restrict__ We0, const float4* __restrict__ We1,
    const float4* __restrict__ We2, const float4* __restrict__ We3,
    float4* __restrict__ out4)
{
    extern __shared__ float sm[];
    float* Wsm = sm;                       // up to 24*512 floats
    float* xrs = sm + 24 * 512;            // 12*48 floats
    int*   ibuf = (int*)(xrs + 12 * 48);   // 16 ints

    embed_expert<48, false>(x4, We3, out4, Wsm, xrs, ibuf);
    embed_expert<24, true >(x4, We2, out4, Wsm, xrs, ibuf);
    embed_expert<16, true >(x4, We1, out4, Wsm, xrs, ibuf);
    embed_expert< 8, true >(x4, We0, out4, Wsm, xrs, ibuf);

    // last block out resets routing state for the next graph replay
    if (threadIdx.x == 0) {
        int d = atomicAdd(&g_done, 1);
        if (d == (int)gridDim.x - 1) {
            g_counts[0] = 0; g_counts[1] = 0; g_counts[2] = 0; g_counts[3] = 0;
            g_cursor[0] = 0; g_cursor[1] = 0; g_cursor[2] = 0; g_cursor[3] = 0;
            g_done = 0;
        }
    }
}

// --------------------------- launch ------------------------------------------
extern "C" void kernel_launch(void* const* d_in, const int* in_sizes, int n_in,
                              void* d_out, int out_size) {
    const float* x  = (const float*)d_in[0];
    const float* un = (const float*)d_in[1];
    const float* W1 = (const float*)d_in[2];
    const float* b1 = (const float*)d_in[3];
    const float* W2 = (const float*)d_in[4];
    const float* b2 = (const float*)d_in[5];
    const float4* We0 = (const float4*)d_in[6];
    const float4* We1 = (const float4*)d_in[7];
    const float4* We2 = (const float4*)d_in[8];
    const float4* We3 = (const float4*)d_in[9];
    float*  out  = (float*)d_out;
    float4* out4 = (float4*)d_out;
    const float4* x4 = (const float4*)d_in[0];

    int write_mode = 0;
    if ((long long)out_size >= XP_ELEMS + 1 + 28672) write_mode = 2;
    else if ((long long)out_size >= XP_ELEMS + 1)    write_mode = 1;

    const int SMEM = (24 * 512 + 12 * 48) * 4 + 64;   // 51520 bytes
    cudaFuncSetAttribute(embed_fused_kernel,
                         cudaFuncAttributeMaxDynamicSharedMemorySize, SMEM);

    router_kernel<<<448, 64>>>(x, un, W1, b1, W2, b2, out, write_mode);
    embed_fused_kernel<<<592, 256, SMEM>>>(x4, We0, We1, We2, We3, out4);
    (void)in_sizes; (void)n_in;
}